// round 8
// baseline (speedup 1.0000x reference)
#include <cuda_runtime.h>
#include <math.h>
#include <stdint.h>

#define Tn 64
#define Bn 32
#define Hn 1024
#define Sn 64
#define Gn 4096
#define NB 128
#define NT 512

// smem float offsets: buf0 @0 (xs 8192 + ws 8192), buf1 @16384, red @32768, sums @40960
#define BUF_FLOATS 16384
#define RED_OFF    (32768 * 4)
#define SUMS_OFF   (40960 * 4)
#define SMEM_BYTES (41984 * 4)

__device__ float g_pre[(size_t)Tn * Bn * Gn];
__device__ float g_h[2][2 * Bn * Hn];
__device__ float g_c[2 * Bn * Hn];
__device__ float g_gamma[Bn * Hn];
__device__ float g_opart[Bn * Hn];
__device__ float g_ctx[Bn * Hn];
__device__ volatile unsigned g_flag[NB];
__device__ volatile unsigned g_rel;

// ---------------- primitives ----------------
__device__ __forceinline__ void ffma2(unsigned long long& d, unsigned long long a,
                                      unsigned long long b) {
    asm volatile("fma.rn.f32x2 %0, %1, %2, %0;" : "+l"(d) : "l"(a), "l"(b));
}
__device__ __forceinline__ void cp16(uint32_t saddr, const void* g) {
    asm volatile("cp.async.cg.shared.global [%0], [%1], 16;" :: "r"(saddr), "l"(g));
}
#define CP_COMMIT() asm volatile("cp.async.commit_group;" ::: "memory")
#define CP_WAIT1()  asm volatile("cp.async.wait_group 1;" ::: "memory")
__device__ __forceinline__ unsigned ld_acq(volatile unsigned* p) {
    unsigned v;
    asm volatile("ld.acquire.gpu.u32 %0, [%1];" : "=r"(v) : "l"((const unsigned*)p) : "memory");
    return v;
}
__device__ __forceinline__ void st_rel(volatile unsigned* p, unsigned v) {
    asm volatile("st.release.gpu.u32 [%0], %1;" :: "l"((unsigned*)p), "r"(v) : "memory");
}

// grid barrier: per-block flags + block-0 collector; monotonic targets across replays
__device__ void gsync(unsigned tgt) {
    __syncthreads();
    if (blockIdx.x == 0) {
        const int t = threadIdx.x;
        if (t > 0 && t < NB)
            while ((int)(ld_acq(&g_flag[t]) - tgt) < 0) __nanosleep(64);
        __syncthreads();
        if (t == 0) { __threadfence(); st_rel(&g_rel, tgt); }
    } else {
        if (threadIdx.x == 0) {
            st_rel(&g_flag[blockIdx.x], tgt);
            while ((int)(ld_acq(&g_rel) - tgt) < 0) __nanosleep(64);
            __threadfence();   // scope>=cluster -> CCTL.IVALL: invalidate stale L1
        }
    }
    __syncthreads();
}

// ---------------- tiled GEMM (full-K per block, f32x2 inner, cp.async pipeline) ----
struct TileArgs {
    const float *X1, *X2;   // X2 used for k>=1024
    const float *W1, *W2;   // W2 used for k>=1024
    int ldw;
    int col0;               // linear col map: col = col0 + c
    int interleave;         // 1: col = (c>>3)*1024 + jbase + (c&7)  (gate interleave)
    int jbase;
    const int* gather; int m0;
    int nch;                // K/256
};

template<int CQ>   // NCOL = 4*CQ; thread grid: CQ(c) x 8(b) x (64/CQ)(k-slices)
__device__ __forceinline__ void stage_chunk(const TileArgs& a, int ch, char* smem, int p) {
    const int koff0 = ch * 256;
    const float* X = (koff0 >= 1024) ? a.X2 : a.X1;
    const float* W = (koff0 >= 1024) ? a.W2 : a.W1;
    const int koff = koff0 & 1023;
    const uint32_t xb = (uint32_t)__cvta_generic_to_shared(smem) + p * (BUF_FLOATS * 4);
    const uint32_t wb = xb + 32768;
    const int tid = threadIdx.x;
    #pragma unroll
    for (int i = 0; i < 4; i++) {              // X: 32 rows x 64 float4
        const int e = tid + i * 512;
        const int row = e >> 6, k4 = e & 63;
        const int grow = a.gather ? __ldg(a.gather + a.m0 + row) : row;
        cp16(xb + (uint32_t)(row * 64 + (k4 ^ (row & 7))) * 16,
             X + (size_t)grow * Hn + koff + k4 * 4);
    }
    #pragma unroll
    for (int i = 0; i < CQ / 2; i++) {         // W: 4*CQ rows x 64 float4
        const int e = tid + i * 512;
        const int c = e >> 6, k4 = e & 63;
        const int grow = a.interleave ? ((c >> 3) * Hn + a.jbase + (c & 7)) : (a.col0 + c);
        cp16(wb + (uint32_t)(c * 64 + (k4 ^ (c & 7))) * 16,
             W + (size_t)grow * a.ldw + koff + k4 * 4);
    }
    CP_COMMIT();
}

__device__ __forceinline__ float fold2(unsigned long long a, unsigned long long b) {
    return __uint_as_float((unsigned)a) + __uint_as_float((unsigned)(a >> 32)) +
           __uint_as_float((unsigned)b) + __uint_as_float((unsigned)(b >> 32));
}

template<int CQ>
__device__ void gemm_tile(const TileArgs& a, char* smem) {
    const int tid = threadIdx.x;
    const int cq = tid % CQ, bq = (tid / CQ) % 8, ks = tid / (CQ * 8);
    unsigned long long acc[2][4][4];
    #pragma unroll
    for (int i = 0; i < 4; i++)
        #pragma unroll
        for (int j = 0; j < 4; j++) { acc[0][i][j] = 0ull; acc[1][i][j] = 0ull; }

    stage_chunk<CQ>(a, 0, smem, 0);
    for (int ch = 0; ch < a.nch; ch++) {
        if (ch + 1 < a.nch) stage_chunk<CQ>(a, ch + 1, smem, (ch + 1) & 1);
        else CP_COMMIT();
        CP_WAIT1();
        __syncthreads();
        const float* xb = (const float*)(smem + (ch & 1) * (BUF_FLOATS * 4));
        const float* wb = xb + 8192;
        #pragma unroll
        for (int u = 0; u < CQ; u++) {
            const int k4 = ks * CQ + u;
            unsigned long long xr[4][2], wr[4][2];
            #pragma unroll
            for (int i = 0; i < 4; i++) {
                const ulonglong2 v = *(const ulonglong2*)(xb + ((bq + 8 * i) * 64 + (k4 ^ bq)) * 4);
                xr[i][0] = v.x; xr[i][1] = v.y;
            }
            #pragma unroll
            for (int j = 0; j < 4; j++) {
                const int c = cq + CQ * j;
                const ulonglong2 v = *(const ulonglong2*)(wb + (c * 64 + (k4 ^ (c & 7))) * 4);
                wr[j][0] = v.x; wr[j][1] = v.y;
            }
            #pragma unroll
            for (int i = 0; i < 4; i++)
                #pragma unroll
                for (int j = 0; j < 4; j++) {
                    ffma2(acc[0][i][j], xr[i][0], wr[j][0]);
                    ffma2(acc[1][i][j], xr[i][1], wr[j][1]);
                }
        }
        __syncthreads();
    }
    // in-block reduction over 64/CQ k-slices
    const int NOUT = 32 * 4 * CQ, KS = 64 / CQ;
    float* red = (float*)(smem + RED_OFF);
    #pragma unroll
    for (int i = 0; i < 4; i++) {
        const int b = bq + 8 * i;
        float4 v;
        v.x = fold2(acc[0][i][0], acc[1][i][0]);
        v.y = fold2(acc[0][i][1], acc[1][i][1]);
        v.z = fold2(acc[0][i][2], acc[1][i][2]);
        v.w = fold2(acc[0][i][3], acc[1][i][3]);
        *(float4*)(red + ks * NOUT + b * (4 * CQ) + cq * 4) = v;
    }
    __syncthreads();
    float* sums = (float*)(smem + SUMS_OFF);
    for (int o = tid; o < NOUT; o += NT) {
        float s = 0.f;
        #pragma unroll
        for (int k = 0; k < KS; k++) s += red[k * NOUT + o];
        sums[o] = s;
    }
    __syncthreads();
}
// sums layout: o = b*4CQ + cl, cl = cq*4 + j, actual local col c = (cl>>2) + CQ*(cl&3)
// interleave (CQ=8): c's gate q = cl&3, j-index jj = cl>>2 -> sums[b*32+jj*4 .. +4] = gates i,f,g,o

// ---------------- epilogues ----------------
__device__ __forceinline__ void lstm_epi(const float* sums, int tile, int t, int layer,
    const float* b_ih, const float* b_hh, float* hNew, float* cSt) {
    const int tid = threadIdx.x;
    if (tid < 256) {
        const int b = tid & 31, jj = tid >> 5;
        const int col = tile * 8 + jj;
        const float4 g = *(const float4*)(sums + b * 32 + jj * 4);
        const float* bi = b_ih + layer * Gn;
        const float* bh = b_hh + layer * Gn;
        float gi = g.x + bi[col] + bh[col];
        float gf = g.y + bi[Hn + col] + bh[Hn + col];
        float gg = g.z + bi[2 * Hn + col] + bh[2 * Hn + col];
        float go = g.w + bi[3 * Hn + col] + bh[3 * Hn + col];
        if (layer == 0) {
            const float* pr = g_pre + ((size_t)t * Bn + b) * Gn;
            gi += pr[col]; gf += pr[Hn + col]; gg += pr[2 * Hn + col]; go += pr[3 * Hn + col];
        }
        gi = 1.f / (1.f + expf(-gi));
        gf = 1.f / (1.f + expf(-gf));
        gg = tanhf(gg);
        go = 1.f / (1.f + expf(-go));
        float* c = cSt + layer * Bn * Hn;
        const float cn = gf * c[b * Hn + col] + gi * gg;
        c[b * Hn + col] = cn;
        (hNew + layer * Bn * Hn)[b * Hn + col] = go * tanhf(cn);
    }
    __syncthreads();
}

__device__ void attn(const float* __restrict__ contexts, char* smem) {
    const int b = blockIdx.x, tid = threadIdx.x;
    float* gam = (float*)smem;
    float* sc = gam + Hn;
    for (int j = tid; j < Hn; j += NT) gam[j] = g_gamma[b * Hn + j];
    __syncthreads();
    const int w = tid >> 5, lane = tid & 31;
    for (int s = w; s < Sn; s += 16) {
        const float* cr = contexts + ((size_t)b * Sn + s) * Hn;
        float p = 0.f;
        for (int j = lane; j < Hn; j += 32) p += cr[j] * gam[j];
        #pragma unroll
        for (int o = 16; o; o >>= 1) p += __shfl_down_sync(0xffffffffu, p, o);
        if (!lane) sc[s] = p;
    }
    __syncthreads();
    if (tid == 0) {
        float m = -1e30f;
        for (int i = 0; i < Sn; i++) m = fmaxf(m, sc[i]);
        float su = 0.f;
        for (int i = 0; i < Sn; i++) { float e = expf(sc[i] - m); sc[i] = e; su += e; }
        const float inv = 1.f / su;
        for (int i = 0; i < Sn; i++) sc[i] *= inv;
    }
    __syncthreads();
    for (int j = tid; j < Hn; j += NT) {
        float a2 = 0.f;
        #pragma unroll 8
        for (int s = 0; s < Sn; s++) a2 += sc[s] * contexts[((size_t)b * Sn + s) * Hn + j];
        g_ctx[b * Hn + j] = a2;
    }
    __syncthreads();
}

// ---------------- persistent kernel ----------------
__global__ void __launch_bounds__(NT, 1) decoder(
    const int* __restrict__ tokens, const float* __restrict__ contexts,
    const float* __restrict__ emb,
    const float* __restrict__ W_ih, const float* __restrict__ W_hh,
    const float* __restrict__ b_ih, const float* __restrict__ b_hh,
    const float* __restrict__ W_in, const float* __restrict__ b_in,
    const float* __restrict__ W_out, const float* __restrict__ b_out,
    const float* __restrict__ h0, const float* __restrict__ c0,
    float* __restrict__ out)
{
    extern __shared__ char smem[];
    const unsigned base = g_rel;    // stable until first barrier completes
    unsigned ph = 0;
    const int tid = threadIdx.x;
    float* sums = (float*)(smem + SUMS_OFF);

    // state init
    for (int i = blockIdx.x * NT + tid; i < 2 * Bn * Hn; i += NB * NT) {
        g_h[0][i] = h0[i];
        g_c[i] = c0[i];
    }

    // pre-phase: g_pre[t*B+b][gatecol] = emb[tokens] @ W_ih0^T (gate-col layout)
    for (int tt = blockIdx.x; tt < 64 * 128; tt += NB) {
        const int ctile = tt & 127;
        TileArgs a;
        a.X1 = emb; a.X2 = emb; a.W1 = W_ih; a.W2 = W_ih; a.ldw = Hn;
        a.interleave = 1; a.jbase = ctile * 8; a.col0 = 0;
        a.gather = tokens; a.m0 = (tt >> 7) * 32; a.nch = 4;
        gemm_tile<8>(a, smem);
        #pragma unroll
        for (int r = 0; r < 2; r++) {
            const int o = tid + r * 512;
            const int b = o >> 5, cl = o & 31;
            const int col = (cl & 3) * Hn + ctile * 8 + (cl >> 2);
            g_pre[(size_t)(a.m0 + b) * Gn + col] = sums[o];
        }
        __syncthreads();
    }
    gsync(base + ++ph);

    for (int t = 0; t < Tn; t++) {
        const int p = t & 1;
        float* hOld = g_h[p];
        float* hNew = g_h[p ^ 1];

        // A: layer-0 gates = pre[t] + h0_old @ W_hh0^T, fused activation
        {
            TileArgs a;
            a.X1 = hOld; a.X2 = hOld; a.W1 = W_hh; a.W2 = W_hh; a.ldw = Hn;
            a.interleave = 1; a.jbase = blockIdx.x * 8; a.col0 = 0;
            a.gather = nullptr; a.m0 = 0; a.nch = 4;
            gemm_tile<8>(a, smem);
            lstm_epi(sums, blockIdx.x, t, 0, b_ih, b_hh, hNew, g_c);
        }
        gsync(base + ++ph);

        // B: layer-1 gates = h0_new @ W_ih1^T + h1_old @ W_hh1^T (K=2048)
        {
            TileArgs a;
            a.X1 = hNew; a.X2 = hOld + Bn * Hn;
            a.W1 = W_ih + (size_t)Gn * Hn; a.W2 = W_hh + (size_t)Gn * Hn; a.ldw = Hn;
            a.interleave = 1; a.jbase = blockIdx.x * 8; a.col0 = 0;
            a.gather = nullptr; a.m0 = 0; a.nch = 8;
            gemm_tile<8>(a, smem);
            lstm_epi(sums, blockIdx.x, t, 1, b_ih, b_hh, hNew, g_c);
        }
        gsync(base + ++ph);

        // C: gamma = h1 @ W_in^T + b_in (tiles 0..63) | opart = h1 @ W_out[:,H:]^T (64..127)
        {
            const int tl = blockIdx.x;
            TileArgs a;
            a.X1 = hNew + Bn * Hn; a.X2 = a.X1;
            a.interleave = 0; a.jbase = 0; a.gather = nullptr; a.m0 = 0; a.nch = 4;
            if (tl < 64) { a.W1 = W_in; a.W2 = W_in; a.ldw = Hn; a.col0 = tl * 16; }
            else { a.W1 = W_out + Hn; a.W2 = a.W1; a.ldw = 2 * Hn; a.col0 = (tl - 64) * 16; }
            gemm_tile<4>(a, smem);
            const int b = tid >> 4, cl = tid & 15;
            const int col = a.col0 + (cl >> 2) + 4 * (cl & 3);
            const float s = sums[tid];
            if (tl < 64) g_gamma[b * Hn + col] = s + b_in[col];
            else g_opart[b * Hn + col] = s;
            __syncthreads();
        }
        gsync(base + ++ph);

        // D: attention (32 blocks)
        if (blockIdx.x < 32) attn(contexts, smem);
        gsync(base + ++ph);

        // E: out[t] = tanh(ctx @ W_out[:, :H]^T + opart + b_out)
        {
            TileArgs a;
            a.X1 = g_ctx; a.X2 = g_ctx; a.W1 = W_out; a.W2 = W_out; a.ldw = 2 * Hn;
            a.interleave = 0; a.jbase = 0; a.col0 = blockIdx.x * 8;
            a.gather = nullptr; a.m0 = 0; a.nch = 4;
            gemm_tile<2>(a, smem);
            if (tid < 256) {
                const int b = tid >> 3, cl = tid & 7;
                const int col = a.col0 + (cl >> 2) + 2 * (cl & 3);
                out[(size_t)t * Bn * Hn + b * Hn + col] =
                    tanhf(sums[tid] + g_opart[b * Hn + col] + b_out[col]);
            }
            __syncthreads();
        }
        // no barrier needed before next A (disjoint buffers); s1 of next step covers E
    }
    gsync(base + ++ph);

    // emit hT (in g_h[0] after even Tn) and cT
    for (int i = blockIdx.x * NT + tid; i < 2 * Bn * Hn; i += NB * NT) {
        out[(size_t)Tn * Bn * Hn + i] = g_h[0][i];
        out[(size_t)Tn * Bn * Hn + 2 * Bn * Hn + i] = g_c[i];
    }
}

// ---------------- launch ----------------
extern "C" void kernel_launch(void* const* d_in, const int* in_sizes, int n_in,
                              void* d_out, int out_size)
{
    const int*   tokens   = (const int*)  d_in[0];
    const float* h0       = (const float*)d_in[1];
    const float* c0       = (const float*)d_in[2];
    const float* contexts = (const float*)d_in[3];
    const float* emb      = (const float*)d_in[4];
    const float* W_ih     = (const float*)d_in[5];
    const float* W_hh     = (const float*)d_in[6];
    const float* b_ih     = (const float*)d_in[7];
    const float* b_hh     = (const float*)d_in[8];
    const float* W_in     = (const float*)d_in[9];
    const float* b_in     = (const float*)d_in[10];
    const float* W_out    = (const float*)d_in[11];
    const float* b_out    = (const float*)d_in[12];
    float* out = (float*)d_out;

    static bool configured = false;
    if (!configured) {
        cudaFuncSetAttribute(decoder, cudaFuncAttributeMaxDynamicSharedMemorySize, SMEM_BYTES);
        configured = true;
    }
    decoder<<<NB, NT, SMEM_BYTES>>>(tokens, contexts, emb, W_ih, W_hh, b_ih, b_hh,
                                    W_in, b_in, W_out, b_out, h0, c0, out);
}

// round 9
// speedup vs baseline: 1.0010x; 1.0010x over previous
#include <cuda_runtime.h>
#include <math.h>
#include <stdint.h>

#define Tn 64
#define Bn 32
#define Hn 1024
#define Sn 64
#define Gn 4096
#define NB 128
#define NT 512

// smem float offsets: buf0 @0 (xs 8192 + ws 8192), buf1 @16384, red @32768, sums @40960
#define BUF_FLOATS 16384
#define RED_OFF    (32768 * 4)
#define SUMS_OFF   (40960 * 4)
#define SMEM_BYTES (41984 * 4)

__device__ float g_pre[(size_t)Tn * Bn * Gn];
__device__ float g_h[2][2 * Bn * Hn];
__device__ float g_c[2 * Bn * Hn];
__device__ float g_gamma[Bn * Hn];
__device__ float g_opart[Bn * Hn];
__device__ float g_ctx[Bn * Hn];
__device__ volatile unsigned g_flag[NB];
__device__ volatile unsigned g_rel;

// ---------------- primitives ----------------
__device__ __forceinline__ void ffma2(unsigned long long& d, unsigned long long a,
                                      unsigned long long b) {
    asm volatile("fma.rn.f32x2 %0, %1, %2, %0;" : "+l"(d) : "l"(a), "l"(b));
}
__device__ __forceinline__ void cp16(uint32_t saddr, const void* g) {
    asm volatile("cp.async.cg.shared.global [%0], [%1], 16;" :: "r"(saddr), "l"(g));
}
#define CP_COMMIT() asm volatile("cp.async.commit_group;" ::: "memory")
#define CP_WAIT1()  asm volatile("cp.async.wait_group 1;" ::: "memory")
__device__ __forceinline__ unsigned ld_acq(volatile unsigned* p) {
    unsigned v;
    asm volatile("ld.acquire.gpu.u32 %0, [%1];" : "=r"(v) : "l"((const unsigned*)p) : "memory");
    return v;
}
__device__ __forceinline__ void st_rel(volatile unsigned* p, unsigned v) {
    asm volatile("st.release.gpu.u32 [%0], %1;" :: "l"((unsigned*)p), "r"(v) : "memory");
}

// grid barrier: per-block flags + block-0 collector; monotonic targets across replays
__device__ void gsync(unsigned tgt) {
    __syncthreads();
    if (blockIdx.x == 0) {
        const int t = threadIdx.x;
        if (t > 0 && t < NB)
            while ((int)(ld_acq(&g_flag[t]) - tgt) < 0) __nanosleep(64);
        __syncthreads();
        if (t == 0) { __threadfence(); st_rel(&g_rel, tgt); }
    } else {
        if (threadIdx.x == 0) {
            st_rel(&g_flag[blockIdx.x], tgt);
            while ((int)(ld_acq(&g_rel) - tgt) < 0) __nanosleep(64);
            __threadfence();   // scope>=cluster -> CCTL.IVALL: invalidate stale L1
        }
    }
    __syncthreads();
}

// ---------------- tiled GEMM (full-K per block, f32x2 inner, cp.async pipeline) ----
struct TileArgs {
    const float *X1, *X2;   // X2 used for k>=1024
    const float *W1, *W2;   // W2 used for k>=1024
    int ldw;
    int col0;               // linear col map: col = col0 + c
    int interleave;         // 1: col = (c>>3)*1024 + jbase + (c&7)  (gate interleave)
    int jbase;
    const int* gather; int m0;
    int nch;                // K/256
};

template<int CQ>   // NCOL = 4*CQ; thread grid: CQ(c) x 8(b) x (64/CQ)(k-slices)
__device__ __forceinline__ void stage_chunk(const TileArgs& a, int ch, char* smem, int p) {
    const int koff0 = ch * 256;
    const float* X = (koff0 >= 1024) ? a.X2 : a.X1;
    const float* W = (koff0 >= 1024) ? a.W2 : a.W1;
    const int koff = koff0 & 1023;
    const uint32_t xb = (uint32_t)__cvta_generic_to_shared(smem) + p * (BUF_FLOATS * 4);
    const uint32_t wb = xb + 32768;
    const int tid = threadIdx.x;
    #pragma unroll
    for (int i = 0; i < 4; i++) {              // X: 32 rows x 64 float4
        const int e = tid + i * 512;
        const int row = e >> 6, k4 = e & 63;
        const int grow = a.gather ? __ldg(a.gather + a.m0 + row) : row;
        cp16(xb + (uint32_t)(row * 64 + (k4 ^ (row & 7))) * 16,
             X + (size_t)grow * Hn + koff + k4 * 4);
    }
    #pragma unroll
    for (int i = 0; i < CQ / 2; i++) {         // W: 4*CQ rows x 64 float4
        const int e = tid + i * 512;
        const int c = e >> 6, k4 = e & 63;
        const int grow = a.interleave ? ((c >> 3) * Hn + a.jbase + (c & 7)) : (a.col0 + c);
        cp16(wb + (uint32_t)(c * 64 + (k4 ^ (c & 7))) * 16,
             W + (size_t)grow * a.ldw + koff + k4 * 4);
    }
    CP_COMMIT();
}

__device__ __forceinline__ float fold2(unsigned long long a, unsigned long long b) {
    return __uint_as_float((unsigned)a) + __uint_as_float((unsigned)(a >> 32)) +
           __uint_as_float((unsigned)b) + __uint_as_float((unsigned)(b >> 32));
}

template<int CQ>
__device__ void gemm_tile(const TileArgs& a, char* smem) {
    const int tid = threadIdx.x;
    const int cq = tid % CQ, bq = (tid / CQ) % 8, ks = tid / (CQ * 8);
    unsigned long long acc[2][4][4];
    #pragma unroll
    for (int i = 0; i < 4; i++)
        #pragma unroll
        for (int j = 0; j < 4; j++) { acc[0][i][j] = 0ull; acc[1][i][j] = 0ull; }

    stage_chunk<CQ>(a, 0, smem, 0);
    for (int ch = 0; ch < a.nch; ch++) {
        if (ch + 1 < a.nch) stage_chunk<CQ>(a, ch + 1, smem, (ch + 1) & 1);
        else CP_COMMIT();
        CP_WAIT1();
        __syncthreads();
        const float* xb = (const float*)(smem + (ch & 1) * (BUF_FLOATS * 4));
        const float* wb = xb + 8192;
        #pragma unroll
        for (int u = 0; u < CQ; u++) {
            const int k4 = ks * CQ + u;
            unsigned long long xr[4][2], wr[4][2];
            #pragma unroll
            for (int i = 0; i < 4; i++) {
                const ulonglong2 v = *(const ulonglong2*)(xb + ((bq + 8 * i) * 64 + (k4 ^ bq)) * 4);
                xr[i][0] = v.x; xr[i][1] = v.y;
            }
            #pragma unroll
            for (int j = 0; j < 4; j++) {
                const int c = cq + CQ * j;
                const ulonglong2 v = *(const ulonglong2*)(wb + (c * 64 + (k4 ^ (c & 7))) * 4);
                wr[j][0] = v.x; wr[j][1] = v.y;
            }
            #pragma unroll
            for (int i = 0; i < 4; i++)
                #pragma unroll
                for (int j = 0; j < 4; j++) {
                    ffma2(acc[0][i][j], xr[i][0], wr[j][0]);
                    ffma2(acc[1][i][j], xr[i][1], wr[j][1]);
                }
        }
        __syncthreads();
    }
    // in-block reduction over 64/CQ k-slices
    const int NOUT = 32 * 4 * CQ, KS = 64 / CQ;
    float* red = (float*)(smem + RED_OFF);
    #pragma unroll
    for (int i = 0; i < 4; i++) {
        const int b = bq + 8 * i;
        float4 v;
        v.x = fold2(acc[0][i][0], acc[1][i][0]);
        v.y = fold2(acc[0][i][1], acc[1][i][1]);
        v.z = fold2(acc[0][i][2], acc[1][i][2]);
        v.w = fold2(acc[0][i][3], acc[1][i][3]);
        *(float4*)(red + ks * NOUT + b * (4 * CQ) + cq * 4) = v;
    }
    __syncthreads();
    float* sums = (float*)(smem + SUMS_OFF);
    for (int o = tid; o < NOUT; o += NT) {
        float s = 0.f;
        #pragma unroll
        for (int k = 0; k < KS; k++) s += red[k * NOUT + o];
        sums[o] = s;
    }
    __syncthreads();
}
// sums layout: o = b*4CQ + cl, cl = cq*4 + j, actual local col c = (cl>>2) + CQ*(cl&3)
// interleave (CQ=8): c's gate q = cl&3, j-index jj = cl>>2 -> sums[b*32+jj*4 .. +4] = gates i,f,g,o

// ---------------- epilogues ----------------
__device__ __forceinline__ void lstm_epi(const float* sums, int tile, int t, int layer,
    const float* b_ih, const float* b_hh, float* hNew, float* cSt) {
    const int tid = threadIdx.x;
    if (tid < 256) {
        const int b = tid & 31, jj = tid >> 5;
        const int col = tile * 8 + jj;
        const float4 g = *(const float4*)(sums + b * 32 + jj * 4);
        const float* bi = b_ih + layer * Gn;
        const float* bh = b_hh + layer * Gn;
        float gi = g.x + bi[col] + bh[col];
        float gf = g.y + bi[Hn + col] + bh[Hn + col];
        float gg = g.z + bi[2 * Hn + col] + bh[2 * Hn + col];
        float go = g.w + bi[3 * Hn + col] + bh[3 * Hn + col];
        if (layer == 0) {
            const float* pr = g_pre + ((size_t)t * Bn + b) * Gn;
            gi += pr[col]; gf += pr[Hn + col]; gg += pr[2 * Hn + col]; go += pr[3 * Hn + col];
        }
        gi = 1.f / (1.f + expf(-gi));
        gf = 1.f / (1.f + expf(-gf));
        gg = tanhf(gg);
        go = 1.f / (1.f + expf(-go));
        float* c = cSt + layer * Bn * Hn;
        const float cn = gf * c[b * Hn + col] + gi * gg;
        c[b * Hn + col] = cn;
        (hNew + layer * Bn * Hn)[b * Hn + col] = go * tanhf(cn);
    }
    __syncthreads();
}

__device__ void attn(const float* __restrict__ contexts, char* smem) {
    const int b = blockIdx.x, tid = threadIdx.x;
    float* gam = (float*)smem;
    float* sc = gam + Hn;
    for (int j = tid; j < Hn; j += NT) gam[j] = g_gamma[b * Hn + j];
    __syncthreads();
    const int w = tid >> 5, lane = tid & 31;
    for (int s = w; s < Sn; s += 16) {
        const float* cr = contexts + ((size_t)b * Sn + s) * Hn;
        float p = 0.f;
        for (int j = lane; j < Hn; j += 32) p += cr[j] * gam[j];
        #pragma unroll
        for (int o = 16; o; o >>= 1) p += __shfl_down_sync(0xffffffffu, p, o);
        if (!lane) sc[s] = p;
    }
    __syncthreads();
    if (tid == 0) {
        float m = -1e30f;
        for (int i = 0; i < Sn; i++) m = fmaxf(m, sc[i]);
        float su = 0.f;
        for (int i = 0; i < Sn; i++) { float e = expf(sc[i] - m); sc[i] = e; su += e; }
        const float inv = 1.f / su;
        for (int i = 0; i < Sn; i++) sc[i] *= inv;
    }
    __syncthreads();
    for (int j = tid; j < Hn; j += NT) {
        float a2 = 0.f;
        #pragma unroll 8
        for (int s = 0; s < Sn; s++) a2 += sc[s] * contexts[((size_t)b * Sn + s) * Hn + j];
        g_ctx[b * Hn + j] = a2;
    }
    __syncthreads();
}

// ---------------- persistent kernel ----------------
__global__ void __launch_bounds__(NT, 1) decoder(
    const int* __restrict__ tokens, const float* __restrict__ contexts,
    const float* __restrict__ emb,
    const float* __restrict__ W_ih, const float* __restrict__ W_hh,
    const float* __restrict__ b_ih, const float* __restrict__ b_hh,
    const float* __restrict__ W_in, const float* __restrict__ b_in,
    const float* __restrict__ W_out, const float* __restrict__ b_out,
    const float* __restrict__ h0, const float* __restrict__ c0,
    float* __restrict__ out)
{
    extern __shared__ char smem[];
    const unsigned base = g_rel;    // stable until first barrier completes
    unsigned ph = 0;
    const int tid = threadIdx.x;
    float* sums = (float*)(smem + SUMS_OFF);

    // state init
    for (int i = blockIdx.x * NT + tid; i < 2 * Bn * Hn; i += NB * NT) {
        g_h[0][i] = h0[i];
        g_c[i] = c0[i];
    }

    // pre-phase: g_pre[t*B+b][gatecol] = emb[tokens] @ W_ih0^T (gate-col layout)
    for (int tt = blockIdx.x; tt < 64 * 128; tt += NB) {
        const int ctile = tt & 127;
        TileArgs a;
        a.X1 = emb; a.X2 = emb; a.W1 = W_ih; a.W2 = W_ih; a.ldw = Hn;
        a.interleave = 1; a.jbase = ctile * 8; a.col0 = 0;
        a.gather = tokens; a.m0 = (tt >> 7) * 32; a.nch = 4;
        gemm_tile<8>(a, smem);
        #pragma unroll
        for (int r = 0; r < 2; r++) {
            const int o = tid + r * 512;
            const int b = o >> 5, cl = o & 31;
            const int col = (cl & 3) * Hn + ctile * 8 + (cl >> 2);
            g_pre[(size_t)(a.m0 + b) * Gn + col] = sums[o];
        }
        __syncthreads();
    }
    gsync(base + ++ph);

    for (int t = 0; t < Tn; t++) {
        const int p = t & 1;
        float* hOld = g_h[p];
        float* hNew = g_h[p ^ 1];

        // A: layer-0 gates = pre[t] + h0_old @ W_hh0^T, fused activation
        {
            TileArgs a;
            a.X1 = hOld; a.X2 = hOld; a.W1 = W_hh; a.W2 = W_hh; a.ldw = Hn;
            a.interleave = 1; a.jbase = blockIdx.x * 8; a.col0 = 0;
            a.gather = nullptr; a.m0 = 0; a.nch = 4;
            gemm_tile<8>(a, smem);
            lstm_epi(sums, blockIdx.x, t, 0, b_ih, b_hh, hNew, g_c);
        }
        gsync(base + ++ph);

        // B: layer-1 gates = h0_new @ W_ih1^T + h1_old @ W_hh1^T (K=2048)
        {
            TileArgs a;
            a.X1 = hNew; a.X2 = hOld + Bn * Hn;
            a.W1 = W_ih + (size_t)Gn * Hn; a.W2 = W_hh + (size_t)Gn * Hn; a.ldw = Hn;
            a.interleave = 1; a.jbase = blockIdx.x * 8; a.col0 = 0;
            a.gather = nullptr; a.m0 = 0; a.nch = 8;
            gemm_tile<8>(a, smem);
            lstm_epi(sums, blockIdx.x, t, 1, b_ih, b_hh, hNew, g_c);
        }
        gsync(base + ++ph);

        // C: gamma = h1 @ W_in^T + b_in (tiles 0..63) | opart = h1 @ W_out[:,H:]^T (64..127)
        {
            const int tl = blockIdx.x;
            TileArgs a;
            a.X1 = hNew + Bn * Hn; a.X2 = a.X1;
            a.interleave = 0; a.jbase = 0; a.gather = nullptr; a.m0 = 0; a.nch = 4;
            if (tl < 64) { a.W1 = W_in; a.W2 = W_in; a.ldw = Hn; a.col0 = tl * 16; }
            else { a.W1 = W_out + Hn; a.W2 = a.W1; a.ldw = 2 * Hn; a.col0 = (tl - 64) * 16; }
            gemm_tile<4>(a, smem);
            const int b = tid >> 4, cl = tid & 15;
            const int col = a.col0 + (cl >> 2) + 4 * (cl & 3);
            const float s = sums[tid];
            if (tl < 64) g_gamma[b * Hn + col] = s + b_in[col];
            else g_opart[b * Hn + col] = s;
            __syncthreads();
        }
        gsync(base + ++ph);

        // D: attention (32 blocks)
        if (blockIdx.x < 32) attn(contexts, smem);
        gsync(base + ++ph);

        // E: out[t] = tanh(ctx @ W_out[:, :H]^T + opart + b_out)
        {
            TileArgs a;
            a.X1 = g_ctx; a.X2 = g_ctx; a.W1 = W_out; a.W2 = W_out; a.ldw = 2 * Hn;
            a.interleave = 0; a.jbase = 0; a.col0 = blockIdx.x * 8;
            a.gather = nullptr; a.m0 = 0; a.nch = 4;
            gemm_tile<2>(a, smem);
            if (tid < 256) {
                const int b = tid >> 3, cl = tid & 7;
                const int col = a.col0 + (cl >> 2) + 2 * (cl & 3);
                out[(size_t)t * Bn * Hn + b * Hn + col] =
                    tanhf(sums[tid] + g_opart[b * Hn + col] + b_out[col]);
            }
            __syncthreads();
        }
        // no barrier needed before next A (disjoint buffers); s1 of next step covers E
    }
    gsync(base + ++ph);

    // emit hT (in g_h[0] after even Tn) and cT
    for (int i = blockIdx.x * NT + tid; i < 2 * Bn * Hn; i += NB * NT) {
        out[(size_t)Tn * Bn * Hn + i] = g_h[0][i];
        out[(size_t)Tn * Bn * Hn + 2 * Bn * Hn + i] = g_c[i];
    }
}

// ---------------- launch ----------------
extern "C" void kernel_launch(void* const* d_in, const int* in_sizes, int n_in,
                              void* d_out, int out_size)
{
    const int*   tokens   = (const int*)  d_in[0];
    const float* h0       = (const float*)d_in[1];
    const float* c0       = (const float*)d_in[2];
    const float* contexts = (const float*)d_in[3];
    const float* emb      = (const float*)d_in[4];
    const float* W_ih     = (const float*)d_in[5];
    const float* W_hh     = (const float*)d_in[6];
    const float* b_ih     = (const float*)d_in[7];
    const float* b_hh     = (const float*)d_in[8];
    const float* W_in     = (const float*)d_in[9];
    const float* b_in     = (const float*)d_in[10];
    const float* W_out    = (const float*)d_in[11];
    const float* b_out    = (const float*)d_in[12];
    float* out = (float*)d_out;

    static bool configured = false;
    if (!configured) {
        cudaFuncSetAttribute(decoder, cudaFuncAttributeMaxDynamicSharedMemorySize, SMEM_BYTES);
        configured = true;
    }
    decoder<<<NB, NT, SMEM_BYTES>>>(tokens, contexts, emb, W_ih, W_hh, b_ih, b_hh,
                                    W_in, b_in, W_out, b_out, h0, c0, out);
}

// round 10
// speedup vs baseline: 1.0593x; 1.0582x over previous
#include <cuda_runtime.h>
#include <math.h>
#include <stdint.h>

#define Tn 64
#define Bn 32
#define Hn 1024
#define Sn 64
#define Gn 4096
#define NB 128
#define NT 512

// smem float offsets: buf0 @0 (xs 8192 + ws 8192), buf1 @16384, red @32768, sums @40960
#define BUF_FLOATS 16384
#define RED_OFF    (32768 * 4)
#define SUMS_OFF   (40960 * 4)
#define SMEM_BYTES (41984 * 4)

__device__ float g_pre[(size_t)Tn * Bn * Gn];
__device__ float g_h[2][2 * Bn * Hn];
__device__ float g_c[2 * Bn * Hn];
__device__ float g_gamma[Bn * Hn];
__device__ float g_opart[Bn * Hn];
__device__ float g_ctx[Bn * Hn];
__device__ unsigned g_ctr;          // cumulative arrival counter
__device__ volatile unsigned g_rel; // cumulative release phase

// ---------------- primitives ----------------
__device__ __forceinline__ void ffma2(unsigned long long& d, unsigned long long a,
                                      unsigned long long b) {
    asm volatile("fma.rn.f32x2 %0, %1, %2, %0;" : "+l"(d) : "l"(a), "l"(b));
}
__device__ __forceinline__ void cp16(uint32_t saddr, const void* g) {
    asm volatile("cp.async.cg.shared.global [%0], [%1], 16;" :: "r"(saddr), "l"(g));
}
#define CP_COMMIT() asm volatile("cp.async.commit_group;" ::: "memory")
#define CP_WAIT1()  asm volatile("cp.async.wait_group 1;" ::: "memory")
__device__ __forceinline__ unsigned ld_acq(volatile unsigned* p) {
    unsigned v;
    asm volatile("ld.acquire.gpu.u32 %0, [%1];" : "=r"(v) : "l"((const unsigned*)p) : "memory");
    return v;
}
__device__ __forceinline__ void st_rel(volatile unsigned* p, unsigned v) {
    asm volatile("st.release.gpu.u32 [%0], %1;" :: "l"((unsigned*)p), "r"(v) : "memory");
}

// grid barrier: cumulative atomic counter, last arriver releases, tight spin.
// tgt is cumulative across graph replays (g_ctr/g_rel never reset; wrap-safe equality).
__device__ void gsync(unsigned tgt) {
    __threadfence();          // make this thread's writes visible at GPU scope
    __syncthreads();
    if (threadIdx.x == 0) {
        const unsigned old = atomicAdd(&g_ctr, 1u);
        if (old == tgt * NB - 1u) {
            st_rel(&g_rel, tgt);
        } else {
            while ((int)(ld_acq(&g_rel) - tgt) < 0) { }
        }
        __threadfence();      // scope>=cluster -> CCTL.IVALL: drop stale L1 lines
    }
    __syncthreads();
}

// ---------------- tiled GEMM (full-K per block, f32x2 inner, cp.async pipeline) ----
struct TileArgs {
    const float *X1, *X2;   // X2 used for k>=1024
    const float *W1, *W2;   // W2 used for k>=1024
    int ldw;
    int col0;               // linear col map: col = col0 + c
    int interleave;         // 1: col = (c>>3)*1024 + jbase + (c&7)  (gate interleave)
    int jbase;
    const int* gather; int m0;
    int nch;                // K/256
};

template<int CQ>   // NCOL = 4*CQ; thread grid: CQ(c) x 8(b) x (64/CQ)(k-slices)
__device__ __forceinline__ void stage_chunk(const TileArgs& a, int ch, char* smem, int p) {
    const int koff0 = ch * 256;
    const float* X = (koff0 >= 1024) ? a.X2 : a.X1;
    const float* W = (koff0 >= 1024) ? a.W2 : a.W1;
    const int koff = koff0 & 1023;
    const uint32_t xb = (uint32_t)__cvta_generic_to_shared(smem) + p * (BUF_FLOATS * 4);
    const uint32_t wb = xb + 32768;
    const int tid = threadIdx.x;
    #pragma unroll
    for (int i = 0; i < 4; i++) {              // X: 32 rows x 64 float4
        const int e = tid + i * 512;
        const int row = e >> 6, k4 = e & 63;
        const int grow = a.gather ? __ldg(a.gather + a.m0 + row) : row;
        cp16(xb + (uint32_t)(row * 64 + (k4 ^ (row & 7))) * 16,
             X + (size_t)grow * Hn + koff + k4 * 4);
    }
    #pragma unroll
    for (int i = 0; i < CQ / 2; i++) {         // W: 4*CQ rows x 64 float4
        const int e = tid + i * 512;
        const int c = e >> 6, k4 = e & 63;
        const int grow = a.interleave ? ((c >> 3) * Hn + a.jbase + (c & 7)) : (a.col0 + c);
        cp16(wb + (uint32_t)(c * 64 + (k4 ^ (c & 7))) * 16,
             W + (size_t)grow * a.ldw + koff + k4 * 4);
    }
    CP_COMMIT();
}

__device__ __forceinline__ float fold2(unsigned long long a, unsigned long long b) {
    return __uint_as_float((unsigned)a) + __uint_as_float((unsigned)(a >> 32)) +
           __uint_as_float((unsigned)b) + __uint_as_float((unsigned)(b >> 32));
}

template<int CQ>
__device__ void gemm_tile(const TileArgs& a, char* smem) {
    const int tid = threadIdx.x;
    const int cq = tid % CQ, bq = (tid / CQ) % 8, ks = tid / (CQ * 8);
    unsigned long long acc[2][4][4];
    #pragma unroll
    for (int i = 0; i < 4; i++)
        #pragma unroll
        for (int j = 0; j < 4; j++) { acc[0][i][j] = 0ull; acc[1][i][j] = 0ull; }

    stage_chunk<CQ>(a, 0, smem, 0);
    for (int ch = 0; ch < a.nch; ch++) {
        if (ch + 1 < a.nch) stage_chunk<CQ>(a, ch + 1, smem, (ch + 1) & 1);
        else CP_COMMIT();
        CP_WAIT1();
        __syncthreads();
        const float* xb = (const float*)(smem + (ch & 1) * (BUF_FLOATS * 4));
        const float* wb = xb + 8192;
        #pragma unroll
        for (int u = 0; u < CQ; u++) {
            const int k4 = ks * CQ + u;
            unsigned long long xr[4][2], wr[4][2];
            #pragma unroll
            for (int i = 0; i < 4; i++) {
                const ulonglong2 v = *(const ulonglong2*)(xb + ((bq + 8 * i) * 64 + (k4 ^ bq)) * 4);
                xr[i][0] = v.x; xr[i][1] = v.y;
            }
            #pragma unroll
            for (int j = 0; j < 4; j++) {
                const int c = cq + CQ * j;
                const ulonglong2 v = *(const ulonglong2*)(wb + (c * 64 + (k4 ^ (c & 7))) * 4);
                wr[j][0] = v.x; wr[j][1] = v.y;
            }
            #pragma unroll
            for (int i = 0; i < 4; i++)
                #pragma unroll
                for (int j = 0; j < 4; j++) {
                    ffma2(acc[0][i][j], xr[i][0], wr[j][0]);
                    ffma2(acc[1][i][j], xr[i][1], wr[j][1]);
                }
        }
        __syncthreads();
    }
    // in-block reduction over 64/CQ k-slices
    const int NOUT = 32 * 4 * CQ, KS = 64 / CQ;
    float* red = (float*)(smem + RED_OFF);
    #pragma unroll
    for (int i = 0; i < 4; i++) {
        const int b = bq + 8 * i;
        float4 v;
        v.x = fold2(acc[0][i][0], acc[1][i][0]);
        v.y = fold2(acc[0][i][1], acc[1][i][1]);
        v.z = fold2(acc[0][i][2], acc[1][i][2]);
        v.w = fold2(acc[0][i][3], acc[1][i][3]);
        *(float4*)(red + ks * NOUT + b * (4 * CQ) + cq * 4) = v;
    }
    __syncthreads();
    float* sums = (float*)(smem + SUMS_OFF);
    for (int o = tid; o < NOUT; o += NT) {
        float s = 0.f;
        #pragma unroll
        for (int k = 0; k < KS; k++) s += red[k * NOUT + o];
        sums[o] = s;
    }
    __syncthreads();
}
// sums layout: o = b*4CQ + cl, cl = cq*4 + j, actual local col c = (cl>>2) + CQ*(cl&3)
// interleave (CQ=8): c's gate q = cl&3, jj = cl>>2 -> sums[b*32+jj*4 .. +4] = gates i,f,g,o

// ---------------- epilogues ----------------
__device__ __forceinline__ void lstm_epi(const float* sums, int tile, int t, int layer,
    const float* b_ih, const float* b_hh, float* hNew, float* cSt) {
    const int tid = threadIdx.x;
    if (tid < 256) {
        const int b = tid & 31, jj = tid >> 5;
        const int col = tile * 8 + jj;
        const float4 g = *(const float4*)(sums + b * 32 + jj * 4);
        const float* bi = b_ih + layer * Gn;
        const float* bh = b_hh + layer * Gn;
        float gi = g.x + bi[col] + bh[col];
        float gf = g.y + bi[Hn + col] + bh[Hn + col];
        float gg = g.z + bi[2 * Hn + col] + bh[2 * Hn + col];
        float go = g.w + bi[3 * Hn + col] + bh[3 * Hn + col];
        if (layer == 0) {
            const float* pr = g_pre + ((size_t)t * Bn + b) * Gn;
            gi += pr[col]; gf += pr[Hn + col]; gg += pr[2 * Hn + col]; go += pr[3 * Hn + col];
        }
        gi = 1.f / (1.f + expf(-gi));
        gf = 1.f / (1.f + expf(-gf));
        gg = tanhf(gg);
        go = 1.f / (1.f + expf(-go));
        float* c = cSt + layer * Bn * Hn;
        const float cn = gf * c[b * Hn + col] + gi * gg;
        c[b * Hn + col] = cn;
        (hNew + layer * Bn * Hn)[b * Hn + col] = go * tanhf(cn);
    }
    __syncthreads();
}

__device__ void attn(const float* __restrict__ contexts, char* smem) {
    const int b = blockIdx.x, tid = threadIdx.x;
    float* gam = (float*)smem;
    float* sc = gam + Hn;
    for (int j = tid; j < Hn; j += NT) gam[j] = g_gamma[b * Hn + j];
    __syncthreads();
    const int w = tid >> 5, lane = tid & 31;
    for (int s = w; s < Sn; s += 16) {
        const float* cr = contexts + ((size_t)b * Sn + s) * Hn;
        float p = 0.f;
        for (int j = lane; j < Hn; j += 32) p += cr[j] * gam[j];
        #pragma unroll
        for (int o = 16; o; o >>= 1) p += __shfl_down_sync(0xffffffffu, p, o);
        if (!lane) sc[s] = p;
    }
    __syncthreads();
    if (tid == 0) {
        float m = -1e30f;
        for (int i = 0; i < Sn; i++) m = fmaxf(m, sc[i]);
        float su = 0.f;
        for (int i = 0; i < Sn; i++) { float e = expf(sc[i] - m); sc[i] = e; su += e; }
        const float inv = 1.f / su;
        for (int i = 0; i < Sn; i++) sc[i] *= inv;
    }
    __syncthreads();
    for (int j = tid; j < Hn; j += NT) {
        float a2 = 0.f;
        #pragma unroll 8
        for (int s = 0; s < Sn; s++) a2 += sc[s] * contexts[((size_t)b * Sn + s) * Hn + j];
        g_ctx[b * Hn + j] = a2;
    }
    __syncthreads();
}

// ---------------- persistent kernel ----------------
__global__ void __launch_bounds__(NT, 1) decoder(
    const int* __restrict__ tokens, const float* __restrict__ contexts,
    const float* __restrict__ emb,
    const float* __restrict__ W_ih, const float* __restrict__ W_hh,
    const float* __restrict__ b_ih, const float* __restrict__ b_hh,
    const float* __restrict__ W_in, const float* __restrict__ b_in,
    const float* __restrict__ W_out, const float* __restrict__ b_out,
    const float* __restrict__ h0, const float* __restrict__ c0,
    float* __restrict__ out)
{
    extern __shared__ char smem[];
    const unsigned base = g_rel;    // stable: previous replay fully drained
    unsigned ph = 0;
    const int tid = threadIdx.x;
    float* sums = (float*)(smem + SUMS_OFF);

    // state init
    for (int i = blockIdx.x * NT + tid; i < 2 * Bn * Hn; i += NB * NT) {
        g_h[0][i] = h0[i];
        g_c[i] = c0[i];
    }

    // pre-phase: g_pre[t*B+b][gatecol] = emb[tokens] @ W_ih0^T (gate-col layout)
    for (int tt = blockIdx.x; tt < 64 * 128; tt += NB) {
        const int ctile = tt & 127;
        TileArgs a;
        a.X1 = emb; a.X2 = emb; a.W1 = W_ih; a.W2 = W_ih; a.ldw = Hn;
        a.interleave = 1; a.jbase = ctile * 8; a.col0 = 0;
        a.gather = tokens; a.m0 = (tt >> 7) * 32; a.nch = 4;
        gemm_tile<8>(a, smem);
        #pragma unroll
        for (int r = 0; r < 2; r++) {
            const int o = tid + r * 512;
            const int b = o >> 5, cl = o & 31;
            const int col = (cl & 3) * Hn + ctile * 8 + (cl >> 2);
            g_pre[(size_t)(a.m0 + b) * Gn + col] = sums[o];
        }
        __syncthreads();
    }
    gsync(base + ++ph);

    for (int t = 0; t < Tn; t++) {
        const int p = t & 1;
        float* hOld = g_h[p];
        float* hNew = g_h[p ^ 1];

        // A: layer-0 gates = pre[t] + h0_old @ W_hh0^T, fused activation
        {
            TileArgs a;
            a.X1 = hOld; a.X2 = hOld; a.W1 = W_hh; a.W2 = W_hh; a.ldw = Hn;
            a.interleave = 1; a.jbase = blockIdx.x * 8; a.col0 = 0;
            a.gather = nullptr; a.m0 = 0; a.nch = 4;
            gemm_tile<8>(a, smem);
            lstm_epi(sums, blockIdx.x, t, 0, b_ih, b_hh, hNew, g_c);
        }
        gsync(base + ++ph);

        // B: layer-1 gates = h0_new @ W_ih1^T + h1_old @ W_hh1^T (K=2048)
        {
            TileArgs a;
            a.X1 = hNew; a.X2 = hOld + Bn * Hn;
            a.W1 = W_ih + (size_t)Gn * Hn; a.W2 = W_hh + (size_t)Gn * Hn; a.ldw = Hn;
            a.interleave = 1; a.jbase = blockIdx.x * 8; a.col0 = 0;
            a.gather = nullptr; a.m0 = 0; a.nch = 8;
            gemm_tile<8>(a, smem);
            lstm_epi(sums, blockIdx.x, t, 1, b_ih, b_hh, hNew, g_c);
        }
        gsync(base + ++ph);

        // C: gamma = h1 @ W_in^T + b_in  (all 128 blocks, 8 cols each)
        {
            TileArgs a;
            a.X1 = hNew + Bn * Hn; a.X2 = a.X1;
            a.W1 = W_in; a.W2 = W_in; a.ldw = Hn;
            a.interleave = 0; a.jbase = 0; a.col0 = blockIdx.x * 8;
            a.gather = nullptr; a.m0 = 0; a.nch = 4;
            gemm_tile<2>(a, smem);
            if (tid < 256) {
                const int b = tid >> 3, cl = tid & 7;
                const int col = a.col0 + (cl >> 2) + 2 * (cl & 3);
                g_gamma[b * Hn + col] = sums[tid] + b_in[col];
            }
            __syncthreads();
        }
        gsync(base + ++ph);

        // D: attention (blocks 0..31)  ||  opart = h1 @ W_out[:,H:]^T (blocks 32..95)
        if (blockIdx.x < 32) {
            attn(contexts, smem);
        } else if (blockIdx.x < 96) {
            TileArgs a;
            a.X1 = hNew + Bn * Hn; a.X2 = a.X1;
            a.W1 = W_out + Hn; a.W2 = a.W1; a.ldw = 2 * Hn;
            a.interleave = 0; a.jbase = 0; a.col0 = (blockIdx.x - 32) * 16;
            a.gather = nullptr; a.m0 = 0; a.nch = 4;
            gemm_tile<4>(a, smem);
            const int b = tid >> 4, cl = tid & 15;
            const int col = a.col0 + (cl >> 2) + 4 * (cl & 3);
            g_opart[b * Hn + col] = sums[tid];
            __syncthreads();
        }
        gsync(base + ++ph);

        // E: out[t] = tanh(ctx @ W_out[:, :H]^T + opart + b_out)
        {
            TileArgs a;
            a.X1 = g_ctx; a.X2 = g_ctx; a.W1 = W_out; a.W2 = W_out; a.ldw = 2 * Hn;
            a.interleave = 0; a.jbase = 0; a.col0 = blockIdx.x * 8;
            a.gather = nullptr; a.m0 = 0; a.nch = 4;
            gemm_tile<2>(a, smem);
            if (tid < 256) {
                const int b = tid >> 3, cl = tid & 7;
                const int col = a.col0 + (cl >> 2) + 2 * (cl & 3);
                out[(size_t)t * Bn * Hn + b * Hn + col] =
                    tanhf(sums[tid] + g_opart[b * Hn + col] + b_out[col]);
            }
            __syncthreads();
        }
        // no barrier needed before next A (disjoint buffers); next A barrier covers E
    }
    gsync(base + ++ph);

    // emit hT (in g_h[0] after even Tn) and cT
    for (int i = blockIdx.x * NT + tid; i < 2 * Bn * Hn; i += NB * NT) {
        out[(size_t)Tn * Bn * Hn + i] = g_h[0][i];
        out[(size_t)Tn * Bn * Hn + 2 * Bn * Hn + i] = g_c[i];
    }
}

// ---------------- launch ----------------
extern "C" void kernel_launch(void* const* d_in, const int* in_sizes, int n_in,
                              void* d_out, int out_size)
{
    const int*   tokens   = (const int*)  d_in[0];
    const float* h0       = (const float*)d_in[1];
    const float* c0       = (const float*)d_in[2];
    const float* contexts = (const float*)d_in[3];
    const float* emb      = (const float*)d_in[4];
    const float* W_ih     = (const float*)d_in[5];
    const float* W_hh     = (const float*)d_in[6];
    const float* b_ih     = (const float*)d_in[7];
    const float* b_hh     = (const float*)d_in[8];
    const float* W_in     = (const float*)d_in[9];
    const float* b_in     = (const float*)d_in[10];
    const float* W_out    = (const float*)d_in[11];
    const float* b_out    = (const float*)d_in[12];
    float* out = (float*)d_out;

    static bool configured = false;
    if (!configured) {
        cudaFuncSetAttribute(decoder, cudaFuncAttributeMaxDynamicSharedMemorySize, SMEM_BYTES);
        configured = true;
    }
    decoder<<<NB, NT, SMEM_BYTES>>>(tokens, contexts, emb, W_ih, W_hh, b_ih, b_hh,
                                    W_in, b_in, W_out, b_out, h0, c0, out);
}